// round 13
// baseline (speedup 1.0000x reference)
#include <cuda_runtime.h>
#include <cuda_bf16.h>
#include <cstdint>

#define NN 1024
#define LL 64

// scratch (allocation-free rule: device globals)
__device__ __align__(16) float g_preib[NN * LL];        // pre_i + be1
__device__ __align__(16) float g_prejT[32 * NN * 2];    // prej transposed: [(k>>1)][j][k&1]
__device__ float g_Vp[NN * 4];                          // per-quadrant V partials
__device__ __align__(16) float g_newH[NN * LL];
__device__ float g_part[128 * LL];
__device__ __align__(16) __nv_bfloat16 g_Bsw[LL * LL];  // We2^T bf16, SW128-swizzled

// HW tanh f32: 1 MUFU op. NOTE (R12): tanh argument must stay f32 —
// bf16x2-argument variant measured rel_err 2.2e-3 (> 1e-3 gate).
__device__ __forceinline__ float htanh(float x) {
    float y;
    asm("tanh.approx.f32 %0, %1;" : "=f"(y) : "f"(x));
    return y;
}

__device__ __forceinline__ uint32_t smem_u32(const void* p) {
    uint32_t a;
    asm("{ .reg .u64 t; cvta.to.shared.u64 t, %1; cvt.u32.u64 %0, t; }" : "=r"(a) : "l"(p));
    return a;
}
__device__ __forceinline__ void ldsm4(uint32_t* r, uint32_t addr) {
    asm volatile("ldmatrix.sync.aligned.m8n8.x4.shared.b16 {%0,%1,%2,%3}, [%4];"
                 : "=r"(r[0]), "=r"(r[1]), "=r"(r[2]), "=r"(r[3]) : "r"(addr));
}
__device__ __forceinline__ void mma16816(float* c, const uint32_t* a, const uint32_t* b) {
    asm volatile(
        "mma.sync.aligned.m16n8k16.row.col.f32.bf16.bf16.f32 "
        "{%0,%1,%2,%3},{%4,%5,%6,%7},{%8,%9},{%0,%1,%2,%3};"
        : "+f"(c[0]), "+f"(c[1]), "+f"(c[2]), "+f"(c[3])
        : "r"(a[0]), "r"(a[1]), "r"(a[2]), "r"(a[3]), "r"(b[0]), "r"(b[1]));
}
__device__ __forceinline__ uint32_t pkbf2(float a, float b) {
    __nv_bfloat162 h = __floats2bfloat162_rn(a, b);
    return *reinterpret_cast<uint32_t*>(&h);
}

// dynamic smem layout (offsets from 1024-aligned base)
#define OFF_B      0u          // 8KB (B bf16, [n][k] swizzled)
#define OFF_D2     8192u       // 1KB (d2 for 256 j's vs this block's i)
#define OFF_PW     9216u       // 512B (interleaved preib/w1z)
#define OFF_BE2    9728u       // 256B
#define DYN_BYTES  (9984u + 1024u)

// ---------------------------------------------------------------------------
// Kernel 0: blocks 0..NN-1: preib = H@We1[:L]+be1 ; prejT = (H@We1[L:2L])^T
//           block NN: build swizzled bf16 B = We2^T
// ---------------------------------------------------------------------------
__global__ void prep_kernel(const int* __restrict__ cats,
                            const float* __restrict__ LM,
                            const float* __restrict__ We1,
                            const float* __restrict__ be1,
                            const float* __restrict__ We2) {
    int n = blockIdx.x, l = threadIdx.x;
    if (n == NN) {  // buildB
        for (int idx = l; idx < LL * LL; idx += LL) {
            int nn = idx & 63, k = idx >> 6;
            float f = We2[k * LL + nn];
            uint32_t o = (uint32_t)(nn * 128 + 2 * k);
            o = o ^ ((o >> 3) & 0x70);
            *(__nv_bfloat16*)((char*)g_Bsw + o) = __float2bfloat16(f);
        }
        return;
    }
    __shared__ float Hs[LL];
    Hs[l] = LM[cats[n] * LL + l];
    __syncthreads();
    float ai = be1[l], aj = 0.0f;
#pragma unroll
    for (int k = 0; k < LL; k++) {
        float h = Hs[k];
        ai = fmaf(h, We1[k * LL + l], ai);
        aj = fmaf(h, We1[(LL + k) * LL + l], aj);
    }
    g_preib[n * LL + l] = ai;
    g_prejT[(l >> 1) * (NN * 2) + n * 2 + (l & 1)] = aj;
}

// ---------------------------------------------------------------------------
// Kernel 1: pair kernel, 4096 blocks.
// block: i = bid>>2, quad = bid&3; handles j in [quad*256, +256).
// 8 warps x 2 tiles of 16 j-rows. bf16 mma (fp32 accum) C = A @ B.
// A fragments computed directly in mma lane layout from transposed prejT
// (1 line per LDG.64); all tanh in f32 (see htanh note).
// B fragments hoisted to registers once per block.
// ---------------------------------------------------------------------------
__global__ __launch_bounds__(256, 2)
void pair_kernel(const float* __restrict__ coords,
                 const float* __restrict__ We1,
                 const float* __restrict__ be2) {
    extern __shared__ __align__(16) char dyn_raw[];
    char* base = (char*)((((uintptr_t)dyn_raw) + 1023) & ~(uintptr_t)1023);
    const uint32_t sb = smem_u32(base);

    __shared__ float s_red[8];

    float* s_d2  = (float*)(base + OFF_D2);
    float* s_pw  = (float*)(base + OFF_PW);    // [2k]=preib, [2k+1]=w1z
    float* s_be2 = (float*)(base + OFF_BE2);

    const int i    = blockIdx.x >> 2;
    const int quad = blockIdx.x & 3;
    const int jq   = quad * 256;
    const int t = threadIdx.x;
    const int w = t >> 5, lane = t & 31;

    // ---- stage pre-swizzled B (8KB copy), d2, vectors ----
    {
        const uint4* src = (const uint4*)g_Bsw;
        uint4* dst = (uint4*)(base + OFF_B);
        dst[t]       = src[t];
        dst[t + 256] = src[t + 256];
    }
    {
        const float zx = coords[3 * i], zy = coords[3 * i + 1], zz = coords[3 * i + 2];
        int j = jq + t;
        float dx = zx - coords[3 * j];
        float dy = zy - coords[3 * j + 1];
        float dz = zz - coords[3 * j + 2];
        s_d2[t] = dx * dx + dy * dy + dz * dz;
    }
    if (t < LL) {
        s_pw[2 * t]     = g_preib[i * LL + t];
        s_pw[2 * t + 1] = We1[2 * LL * LL + t];
        s_be2[t]        = be2[t];
    }
    __syncthreads();

    // ldmatrix B lane mapping (x4 covers n-pair x k-halves)
    const int brow = lane & 7;
    const int bg   = lane >> 3;
    const uint32_t bns  = (uint32_t)(bg >> 1) * 1024u;
    const uint32_t bks  = (uint32_t)(bg & 1) * 16u;
    const uint32_t xorB = (uint32_t)(brow << 4);
    const uint32_t bB   = sb + OFF_B + bns + (uint32_t)brow * 128u;

    // ---- hoist ALL B fragments into registers (once per block) ----
    uint32_t breg[4][4][4];
#pragma unroll
    for (int ntp = 0; ntp < 4; ntp++)
#pragma unroll
        for (int kk = 0; kk < 4; kk++) {
            uint32_t col = ((uint32_t)(kk * 32) + bks) ^ xorB;
            ldsm4(breg[ntp][kk], bB + (uint32_t)(ntp * 2048) + col);
        }

    // fragment lane mapping
    const int rquad = lane >> 2;           // row within tile (and +8)
    const int cpair = (lane & 3) * 2;      // col pair base
    const int cb = cpair;                  // epilogue be2 col base
    const int chb = cpair >> 1;            // prejT k-pair index base

    float vpart = 0.0f;

#pragma unroll
    for (int tt = 0; tt < 2; tt++) {
        const int tile = w + tt * 8;            // 0..15 within quadrant
        const int jloc = tile * 16;
        const int jbase = jq + jloc;

        // ---------------- phase 1: A fragments directly ----------------
        const float d2a = s_d2[jloc + rquad];
        const float d2b = s_d2[jloc + rquad + 8];
        const float* pT = g_prejT + (jbase + rquad) * 2;

        uint32_t ahi[4][4];
#pragma unroll
        for (int kk = 0; kk < 4; kk++) {
            const int c  = cpair + 16 * kk;
            const int ch = chb + 8 * kk;
            float4 pw0 = *(const float4*)&s_pw[2 * c];
            float4 pw1 = *(const float4*)&s_pw[2 * (c + 8)];
            float2 pA0 = *(const float2*)(pT + ch * (NN * 2));
            float2 pB0 = *(const float2*)(pT + ch * (NN * 2) + 16);
            float2 pA1 = *(const float2*)(pT + (ch + 4) * (NN * 2));
            float2 pB1 = *(const float2*)(pT + (ch + 4) * (NN * 2) + 16);
            ahi[kk][0] = pkbf2(htanh(fmaf(d2a, pw0.y, pw0.x + pA0.x)),
                               htanh(fmaf(d2a, pw0.w, pw0.z + pA0.y)));
            ahi[kk][1] = pkbf2(htanh(fmaf(d2b, pw0.y, pw0.x + pB0.x)),
                               htanh(fmaf(d2b, pw0.w, pw0.z + pB0.y)));
            ahi[kk][2] = pkbf2(htanh(fmaf(d2a, pw1.y, pw1.x + pA1.x)),
                               htanh(fmaf(d2a, pw1.w, pw1.z + pA1.y)));
            ahi[kk][3] = pkbf2(htanh(fmaf(d2b, pw1.y, pw1.x + pB1.x)),
                               htanh(fmaf(d2b, pw1.w, pw1.z + pB1.y)));
        }

        // ---------------- phase 2: MMAs (A and B from registers) --------
        const bool mytile = (jbase <= i) && (i < jbase + 16);
        const int rowi = i - jbase;
#pragma unroll
        for (int ntp = 0; ntp < 4; ntp++) {
            const int n0 = 2 * ntp, nx = n0 + 1;
            float c0[4] = {0.f, 0.f, 0.f, 0.f};
            float c1[4] = {0.f, 0.f, 0.f, 0.f};
#pragma unroll
            for (int kk = 0; kk < 4; kk++) {
                mma16816(c0, ahi[kk], breg[ntp][kk]);
                mma16816(c1, ahi[kk], breg[ntp][kk] + 2);
            }
            float b00 = s_be2[n0 * 8 + cb], b01 = s_be2[n0 * 8 + cb + 1];
            float b10 = s_be2[nx * 8 + cb], b11 = s_be2[nx * 8 + cb + 1];
            float acc0 = htanh(c0[0] + b00) + htanh(c0[1] + b01)
                       + htanh(c1[0] + b10) + htanh(c1[1] + b11);
            float acc1 = htanh(c0[2] + b00) + htanh(c0[3] + b01)
                       + htanh(c1[2] + b10) + htanh(c1[3] + b11);
            if (!(mytile && rquad == rowi))     vpart += acc0;
            if (!(mytile && rquad + 8 == rowi)) vpart += acc1;
        }
    }

    // reduce over warp + block -> Vp[i][quad]
#pragma unroll
    for (int o = 16; o > 0; o >>= 1)
        vpart += __shfl_down_sync(0xffffffffu, vpart, o);
    if (lane == 0) s_red[w] = vpart;
    __syncthreads();
    if (t == 0) {
        float v = 0.f;
#pragma unroll
        for (int q = 0; q < 8; q++) v += s_red[q];
        g_Vp[i * 4 + quad] = v;
    }
}

// ---------------------------------------------------------------------------
// Kernel 2: head. V = sum of 4 quadrant partials.
// ---------------------------------------------------------------------------
__global__ void head_kernel(const int* __restrict__ cats,
                            const float* __restrict__ LM,
                            const float* __restrict__ Wh1,
                            const float* __restrict__ bh1,
                            const float* __restrict__ Wh2,
                            const float* __restrict__ bh2) {
    __shared__ float Hs[LL];
    __shared__ float hhs[LL];
    int n = blockIdx.x, l = threadIdx.x;
    Hs[l] = LM[cats[n] * LL + l];
    __syncthreads();
    float V = (g_Vp[n * 4 + 0] + g_Vp[n * 4 + 1]) + (g_Vp[n * 4 + 2] + g_Vp[n * 4 + 3]);
    float acc = fmaf(V, Wh1[LL * LL + l], bh1[l]);
#pragma unroll
    for (int k = 0; k < LL; k++)
        acc = fmaf(Hs[k], Wh1[k * LL + l], acc);
    hhs[l] = tanhf(acc);
    __syncthreads();
    float acc2 = bh2[l];
#pragma unroll
    for (int k = 0; k < LL; k++)
        acc2 = fmaf(hhs[k], Wh2[k * LL + l], acc2);
    g_newH[n * LL + l] = tanhf(acc2);
}

// ---------------------------------------------------------------------------
// Kernel 3: final1 — 128-block coalesced partial column sums (merged 1-block
// variant measured 9.6us latency-bound in R11; this split is ~4.5+1.0us).
// ---------------------------------------------------------------------------
__global__ void final1_kernel() {
    __shared__ float s[256];
    int b = blockIdx.x, t = threadIdx.x;
    int l = t & 63, r = t >> 6;
    float acc = 0.f;
#pragma unroll
    for (int m = 0; m < 2; m++) {
        int n = b * 8 + r * 2 + m;
        acc += g_newH[n * LL + l];
    }
    s[t] = acc;
    __syncthreads();
    if (t < 64)
        g_part[b * LL + t] = s[t] + s[t + 64] + s[t + 128] + s[t + 192];
}

__global__ void final2_kernel(const float* __restrict__ Wo,
                              const float* __restrict__ bo,
                              float* __restrict__ out) {
    __shared__ float s_w[2];
    int t = threadIdx.x;          // 64 threads
    float h = 0.f;
#pragma unroll
    for (int q = 0; q < 128; q++)
        h += g_part[q * LL + t];
    float v = h * Wo[t];
#pragma unroll
    for (int o = 16; o > 0; o >>= 1)
        v += __shfl_down_sync(0xffffffffu, v, o);
    if ((t & 31) == 0) s_w[t >> 5] = v;
    __syncthreads();
    if (t == 0) out[0] = s_w[0] + s_w[1] + bo[0];
}

// ---------------------------------------------------------------------------
extern "C" void kernel_launch(void* const* d_in, const int* in_sizes, int n_in,
                              void* d_out, int out_size) {
    (void)in_sizes; (void)n_in; (void)out_size;
    const int*   cats   = (const int*)  d_in[0];
    const float* coords = (const float*)d_in[1];
    const float* LM     = (const float*)d_in[2];
    const float* We1    = (const float*)d_in[3];
    const float* be1    = (const float*)d_in[4];
    const float* We2    = (const float*)d_in[5];
    const float* be2    = (const float*)d_in[6];
    const float* Wh1    = (const float*)d_in[7];
    const float* bh1    = (const float*)d_in[8];
    const float* Wh2    = (const float*)d_in[9];
    const float* bh2    = (const float*)d_in[10];
    const float* Wo     = (const float*)d_in[11];
    const float* bo     = (const float*)d_in[12];

    cudaFuncSetAttribute(pair_kernel,
                         cudaFuncAttributeMaxDynamicSharedMemorySize, DYN_BYTES);

    prep_kernel  <<<NN + 1, LL>>>(cats, LM, We1, be1, We2);
    pair_kernel  <<<4096, 256, DYN_BYTES>>>(coords, We1, be2);
    head_kernel  <<<NN, LL>>>(cats, LM, Wh1, bh1, Wh2, bh2);
    final1_kernel<<<128, 256>>>();
    final2_kernel<<<1, 64>>>(Wo, bo, (float*)d_out);
}